// round 17
// baseline (speedup 1.0000x reference)
#include <cuda_runtime.h>
#include <cuda_fp16.h>
#include <cstdint>

// ExRestSelfAtten, round 17: round 16 (tensor-core banded scores via C-frag
// reuse, m16n8k8) + bugfix: explicit zero-init of the smS overlay window.
// Round 16 failed only because OOB band slots were assumed zero but the smS
// overlay (Ah rows 100-123) has uninitialized row-padding bytes.
// 3 GEMMs (h, t=h@M, p=h@(Wv@W2)), fp16 split hi/lo 3-chain, 2 CTAs/SM.

#define B_    1024
#define S_    100
#define IN_   100
#define H_    128
#define MID_  32
#define OUT_  2
#define NTHREADS 256

#define SAH 136   // A row stride (halves)
#define SWH 40    // W-stage row stride (halves)

// SMEM float offsets
#define AH_F   0        // Ah 128x136 halves; rows 100-127 tail = smS overlay
#define AL_F   8704
#define WB_F   17408    // 2 staging buffers x 5120 fl; afterwards: p buffer
#define SB2_F  27776    // cb2 (32 fl)
#define SW3_F  27808
#define SB3_F  27872
#define SMEM_FLOATS 27874
#define SMEM_BYTES  (SMEM_FLOATS * 4)

#define SMS_F  6800     // smS overlay on Ah rows 100..127: [2][100][8]

typedef unsigned long long u64;

__device__ uint4 g_whl[2][2][4][512];          // [w: W1,M][hi/lo][kc][n128xk32]
__device__ uint4 g_wv2[2][4][128];             // [hi/lo][kc][c32xk32]
__device__ float g_cb2[MID_];

// ---------------- helpers ----------------
__device__ __forceinline__ uint32_t smem_u32(const void* p) {
    uint32_t a;
    asm("{ .reg .u64 t; cvta.to.shared.u64 t, %1; cvt.u32.u64 %0, t; }" : "=r"(a) : "l"(p));
    return a;
}
__device__ __forceinline__ void mma_f16(float* c, const uint32_t* a,
                                        uint32_t b0, uint32_t b1) {
    asm volatile(
        "mma.sync.aligned.m16n8k16.row.col.f32.f16.f16.f32 "
        "{%0,%1,%2,%3}, {%4,%5,%6,%7}, {%8,%9}, {%0,%1,%2,%3};"
        : "+f"(c[0]), "+f"(c[1]), "+f"(c[2]), "+f"(c[3])
        : "r"(a[0]), "r"(a[1]), "r"(a[2]), "r"(a[3]), "r"(b0), "r"(b1));
}
__device__ __forceinline__ void mma_k8(float* c, uint32_t a0, uint32_t a1, uint32_t b0) {
    asm volatile(
        "mma.sync.aligned.m16n8k8.row.col.f32.f16.f16.f32 "
        "{%0,%1,%2,%3}, {%4,%5}, {%6}, {%0,%1,%2,%3};"
        : "+f"(c[0]), "+f"(c[1]), "+f"(c[2]), "+f"(c[3])
        : "r"(a0), "r"(a1), "r"(b0));
}
__device__ __forceinline__ void ldm4(uint32_t* r, uint32_t addr) {
    asm volatile("ldmatrix.sync.aligned.m8n8.x4.shared.b16 {%0,%1,%2,%3}, [%4];"
                 : "=r"(r[0]), "=r"(r[1]), "=r"(r[2]), "=r"(r[3]) : "r"(addr));
}
__device__ __forceinline__ void cp16(uint32_t dst, const void* src) {
    asm volatile("cp.async.ca.shared.global [%0], [%1], 16;" :: "r"(dst), "l"(src) : "memory");
}
__device__ __forceinline__ void cp_commit() {
    asm volatile("cp.async.commit_group;" ::: "memory");
}
__device__ __forceinline__ void cp_wait0() {
    asm volatile("cp.async.wait_group 0;" ::: "memory");
}
__device__ __forceinline__ __half2 split_hi2(float v0, float v1, __half2& lo2) {
    __half h0 = __float2half_rn(v0), h1 = __float2half_rn(v1);
    lo2 = __halves2half2(__float2half_rn(v0 - __half2float(h0)),
                         __float2half_rn(v1 - __half2float(h1)));
    return __halves2half2(h0, h1);
}
// split two fp32 into packed f16x2 hi + lo (for C->A fragment reuse)
__device__ __forceinline__ void split_pack(float c0, float c1,
                                           uint32_t& hi, uint32_t& lo) {
    __half2 h = __floats2half2_rn(c0, c1);
    float2 hf = __half22float2(h);
    __half2 l = __floats2half2_rn(c0 - hf.x, c1 - hf.y);
    hi = *reinterpret_cast<uint32_t*>(&h);
    lo = *reinterpret_cast<uint32_t*>(&l);
}

// ---------------- fused prep: 29 blocks ----------------
// 0-3: W1 chunks; 4-19: M eighth-chunks (8 rows); 20-27: Wv@W2 half-chunks
// (16 k-rows); 28: cb2 = b2 + bv@W2.
__global__ void prep_all(const float* __restrict__ W1, const float* __restrict__ Wq,
                         const float* __restrict__ Wk, const float* __restrict__ Wv,
                         const float* __restrict__ W2, const float* __restrict__ bv,
                         const float* __restrict__ b2)
{
    __shared__ float sbuf[6272];
    const int bid = blockIdx.x, tid = threadIdx.x;

    if (bid < 4) {
        float* tile = sbuf;                    // [32 k][129]
        const int kc = bid;
        for (int e = tid; e < 4096; e += 256) {
            int kg = e >> 7, n = e & 127;
            int kglob = kc * 32 + kg;
            tile[kg * 129 + n] = (kglob < IN_) ? W1[kglob * H_ + n] : 0.f;
        }
        __syncthreads();
        __half* dh = (__half*)&g_whl[0][0][kc][0];
        __half* dl = (__half*)&g_whl[0][1][kc][0];
        for (int e = tid; e < 4096; e += 256) {   // e = n*32 + k
            int k = e & 31, n = e >> 5;
            float val = tile[k * 129 + n];
            __half hh = __float2half_rn(val);
            dh[e] = hh;
            dl[e] = __float2half_rn(val - __half2float(hh));
        }
    } else if (bid < 20) {
        // M eighth-chunk: rows a in [kc*32 + q*8, +8)
        const int kc = (bid - 4) >> 2, q = (bid - 4) & 3;
        const int a0 = kc * 32 + q * 8;
        float* sWq = sbuf;                     // [8][128]
        for (int e = tid; e < 1024; e += 256)
            sWq[e] = Wq[(a0 + (e >> 7)) * H_ + (e & 127)];
        __syncthreads();
        const int n = tid & 127, koff = (tid >> 7) * 4;
        float acc[4];
        #pragma unroll
        for (int t = 0; t < 4; t++) acc[t] = 0.f;
        const float4* wkn = (const float4*)(Wk + n * H_);
        for (int i = 0; i < 32; i++) {
            float4 kv = wkn[i];
            #pragma unroll
            for (int t = 0; t < 4; t++) {
                const float* qq = sWq + (koff + t) * 128 + i * 4;
                acc[t] = fmaf(qq[0], kv.x, fmaf(qq[1], kv.y,
                          fmaf(qq[2], kv.z, fmaf(qq[3], kv.w, acc[t]))));
            }
        }
        __half* dh = (__half*)&g_whl[1][0][kc][0];
        __half* dl = (__half*)&g_whl[1][1][kc][0];
        #pragma unroll
        for (int t = 0; t < 4; t++) {
            int k_local = q * 8 + koff + t;
            int e = n * 32 + k_local;
            __half hh = __float2half_rn(acc[t]);
            dh[e] = hh;
            dl[e] = __float2half_rn(acc[t] - __half2float(hh));
        }
    } else if (bid < 28) {
        const int kc = (bid - 20) >> 1, kh = (bid - 20) & 1;
        float* sW2s = sbuf;                    // [128 n][32 c]
        float* sWv  = sbuf + 4096;             // [16 k][128 n]
        for (int e = tid; e < 4096; e += 256)
            sW2s[e] = W2[e];
        for (int e = tid; e < 2048; e += 256)
            sWv[e] = Wv[(kc * 32 + kh * 16 + (e >> 7)) * H_ + (e & 127)];
        __syncthreads();
        __half* dh = (__half*)&g_wv2[0][kc][0];
        __half* dl = (__half*)&g_wv2[1][kc][0];
        #pragma unroll
        for (int i = 0; i < 2; i++) {
            int o = tid + 256 * i;             // 512 outputs
            int k = o >> 5, cc = o & 31;
            float acc = 0.f;
            #pragma unroll 8
            for (int n = 0; n < 128; n++)
                acc = fmaf(sWv[k * 128 + n], sW2s[n * 32 + cc], acc);
            int e = cc * 32 + kh * 16 + k;
            __half hh = __float2half_rn(acc);
            dh[e] = hh;
            dl[e] = __float2half_rn(acc - __half2float(hh));
        }
    } else {
        if (tid < MID_) {
            float acc = b2[tid];
            for (int n = 0; n < 128; n++)
                acc = fmaf(bv[n], W2[n * 32 + tid], acc);
            g_cb2[tid] = acc;
        }
    }
}

// ---------------- main kernel ----------------
__global__ __launch_bounds__(NTHREADS, 2)
void exrest_fused_kernel(const float* __restrict__ x,  const float* __restrict__ b1,
                         const float* __restrict__ W3, const float* __restrict__ b3,
                         const float* __restrict__ pe,
                         float* __restrict__ out, float* __restrict__ wout)
{
    extern __shared__ float sm[];
    __half* Ah = (__half*)sm;
    __half* Al = (__half*)(sm + AL_F);
    float* smS  = sm + SMS_F;                  // overlay on Ah rows 100..127
    float* cb2s = sm + SB2_F;
    float* sW3  = sm + SW3_F;
    float* sb3  = sm + SB3_F;

    const int tid  = threadIdx.x;
    const int lane = tid & 31;
    const int wid  = tid >> 5;                 // 0..7
    const int g    = lane >> 2;
    const int cq   = lane & 3;
    const int nhalf = wid >> 2;                // chunks 0-7: N 64-col half
    const int mrow  = (wid + 3 * nhalf) & 3;   // light (==3) warps spread
    const bool fullM = (mrow < 3);
    const int bb   = blockIdx.x;

    const uint32_t sbase = smem_u32(sm);
    const uint32_t ALOFSB = AL_F * 4;
    const uint32_t WLOFSB = 10240;             // hi image bytes in stage buf

    if (tid < MID_)        cb2s[tid] = g_cb2[tid];
    if (tid < MID_ * OUT_) sW3[tid] = W3[tid];
    if (tid < OUT_)        sb3[tid] = b3[tid];
    {
        const float* xb = x + (long long)bb * (S_ * IN_);
        for (int e = tid; e < 128 * 64; e += NTHREADS) {
            int r = e >> 6, cp = (e & 63) * 2;
            float2 v = make_float2(0.f, 0.f);
            if (r < S_ && cp < IN_)
                v = *(const float2*)(xb + r * IN_ + cp);
            __half2 lo2;
            __half2 hi2 = split_hi2(v.x, v.y, lo2);
            *(__half2*)&Ah[r * SAH + cp] = hi2;
            *(__half2*)&Al[r * SAH + cp] = lo2;
        }
        // BUGFIX (r16): zero the smS overlay incl. row-padding bytes so the
        // unwritten OOB band slots are exactly 0 (benign same-value overlap
        // with the zero rows written above).
        for (int e = tid; e < 1600; e += NTHREADS) smS[e] = 0.f;
    }

    auto stage_chunk = [&](uint32_t base, int nc) {
        if (nc < 8) {
            #pragma unroll
            for (int i = 0; i < 4; i++) {
                int e = tid + 256 * i;
                int img = e >> 9, rem = e & 511;
                uint32_t d = base + (uint32_t)img * WLOFSB
                           + (uint32_t)(rem >> 2) * 80 + (uint32_t)(rem & 3) * 16;
                cp16(d, (const char*)&g_whl[nc >> 2][img][nc & 3][0] + rem * 16);
            }
        } else {
            int pair = nc - 8;
            #pragma unroll
            for (int i = 0; i < 2; i++) {
                int e = tid + 256 * i;
                int img = e >> 8, rem = e & 255;
                int kci = rem >> 7, r2 = rem & 127;
                uint32_t d = base + (uint32_t)img * WLOFSB + (uint32_t)kci * 2560
                           + (uint32_t)(r2 >> 2) * 80 + (uint32_t)(r2 & 3) * 16;
                cp16(d, (const char*)&g_wv2[img][pair * 2 + kci][0] + r2 * 16);
            }
        }
    };

    stage_chunk(sbase + WB_F * 4, 0);
    cp_commit();
    cp_wait0();
    __syncthreads();

    float c[2][8][4];
    #pragma unroll
    for (int mi = 0; mi < 2; mi++)
        #pragma unroll
        for (int nt = 0; nt < 8; nt++)
            #pragma unroll
            for (int rr = 0; rr < 4; rr++) c[mi][nt][rr] = 0.f;

    const float INV_SQRT_H = 0.08838834764831845f;

    const uint32_t aRowByte = (uint32_t)((mrow * 32 + (lane & 15)) * SAH
                                         + ((lane >> 4) << 3)) * 2;
    const uint32_t aRowByteP = (uint32_t)((wid * 16 + (lane & 15)) * SAH
                                          + ((lane >> 4) << 3)) * 2;
    const int bq = lane >> 3;
    const uint32_t bRowHalf = (uint32_t)((nhalf * 64 + ((bq >> 1) << 3) + (lane & 7)) * SWH
                                         + ((bq & 1) << 3));
    const uint32_t bRowHalfP = (uint32_t)((((bq >> 1) << 3) + (lane & 7)) * SWH
                                          + ((bq & 1) << 3));

    for (int cc = 0; cc < 10; cc++) {
        const int p = cc & 1;
        if (cc < 9) {
            stage_chunk(sbase + WB_F * 4 + (uint32_t)(1 - p) * 20480, cc + 1);
            cp_commit();
        }
        const uint32_t wbase = sbase + (uint32_t)WB_F * 4 + (uint32_t)p * 20480;

        if (cc < 8) {
            const int kc = cc & 3;
            #pragma unroll
            for (int ks = 0; ks < 2; ks++) {
                if (cc == 3 && ks == 1) continue;   // x cols 112-127 are zero
                const uint32_t aAddr = sbase + aRowByte + (uint32_t)(kc * 32 + ks * 16) * 2;
                uint32_t ah[2][4], al[2][4];
                ldm4(ah[0], aAddr);
                ldm4(al[0], aAddr + ALOFSB);
                if (fullM) {
                    ldm4(ah[1], aAddr + 16 * SAH * 2);
                    ldm4(al[1], aAddr + ALOFSB + 16 * SAH * 2);
                }
                #pragma unroll
                for (int gi = 0; gi < 4; gi++) {
                    const uint32_t bAddr = wbase
                        + (bRowHalf + (uint32_t)(gi * 16 * SWH) + (uint32_t)(ks * 16)) * 2;
                    uint32_t r4[4], s4[4];
                    ldm4(r4, bAddr);
                    ldm4(s4, bAddr + WLOFSB);
                    const int nt0 = gi * 2, nt1 = gi * 2 + 1;
                    mma_f16(c[0][nt0], ah[0], r4[0], r4[1]);
                    mma_f16(c[0][nt0], ah[0], s4[0], s4[1]);
                    mma_f16(c[0][nt0], al[0], r4[0], r4[1]);
                    mma_f16(c[0][nt1], ah[0], r4[2], r4[3]);
                    mma_f16(c[0][nt1], ah[0], s4[2], s4[3]);
                    mma_f16(c[0][nt1], al[0], r4[2], r4[3]);
                    if (fullM) {
                        mma_f16(c[1][nt0], ah[1], r4[0], r4[1]);
                        mma_f16(c[1][nt0], ah[1], s4[0], s4[1]);
                        mma_f16(c[1][nt0], al[1], r4[0], r4[1]);
                        mma_f16(c[1][nt1], ah[1], r4[2], r4[3]);
                        mma_f16(c[1][nt1], ah[1], s4[2], s4[3]);
                        mma_f16(c[1][nt1], al[1], r4[2], r4[3]);
                    }
                }
            }
        } else if (wid < 7) {                  // p = h @ W_v2 (N=32), 2 kc/chunk
            #pragma unroll
            for (int kci = 0; kci < 2; kci++) {
                const int kcp = (cc - 8) * 2 + kci;
                const uint32_t kbase = wbase + (uint32_t)kci * 2560;
                #pragma unroll
                for (int ks = 0; ks < 2; ks++) {
                    const uint32_t aAddr = sbase + aRowByteP
                                         + (uint32_t)(kcp * 32 + ks * 16) * 2;
                    uint32_t ah[4], al[4];
                    ldm4(ah, aAddr);
                    ldm4(al, aAddr + ALOFSB);
                    #pragma unroll
                    for (int gi = 0; gi < 2; gi++) {
                        const uint32_t bAddr = kbase
                            + (bRowHalfP + (uint32_t)(gi * 16 * SWH) + (uint32_t)(ks * 16)) * 2;
                        uint32_t r4[4], s4[4];
                        ldm4(r4, bAddr);
                        ldm4(s4, bAddr + WLOFSB);
                        const int nt0 = gi * 2, nt1 = gi * 2 + 1;
                        mma_f16(c[0][nt0], ah, r4[0], r4[1]);
                        mma_f16(c[0][nt0], ah, s4[0], s4[1]);
                        mma_f16(c[0][nt0], al, r4[0], r4[1]);
                        mma_f16(c[0][nt1], ah, r4[2], r4[3]);
                        mma_f16(c[0][nt1], ah, s4[2], s4[3]);
                        mma_f16(c[0][nt1], al, r4[2], r4[3]);
                    }
                }
            }
        }

        if (cc == 3) {
            __syncthreads();                   // all ldmatrix reads of A done
            #pragma unroll
            for (int mi = 0; mi < 2; mi++)
                #pragma unroll
                for (int hi = 0; hi < 2; hi++) {
                    int r = mrow * 32 + mi * 16 + hi * 8 + g;
                    if (r < S_) {
                        #pragma unroll
                        for (int nt = 0; nt < 8; nt++) {
                            int col = nhalf * 64 + nt * 8 + 2 * cq;
                            float2 bb1 = *(const float2*)(b1 + col);
                            float2 pp  = *(const float2*)(pe + r * H_ + col);
                            float v0 = c[mi][nt][hi * 2 + 0] + bb1.x;
                            float v1 = c[mi][nt][hi * 2 + 1] + bb1.y;
                            v0 = fmaxf(v0, 0.f) + pp.x;
                            v1 = fmaxf(v1, 0.f) + pp.y;
                            __half2 lo2;
                            __half2 hi2 = split_hi2(v0, v1, lo2);
                            *(__half2*)&Ah[r * SAH + col] = hi2;
                            *(__half2*)&Al[r * SAH + col] = lo2;
                        }
                    }
                }
            #pragma unroll
            for (int mi = 0; mi < 2; mi++)
                #pragma unroll
                for (int nt = 0; nt < 8; nt++)
                    #pragma unroll
                    for (int rr = 0; rr < 4; rr++) c[mi][nt][rr] = 0.f;
        } else if (cc == 7) {
            // ---- banded scores on the tensor pipe: score = t @ h^T (band) ----
            // t C-frags reused as m16n8k8 A-frags (fp16 split, 3 chains);
            // B = h rows j via non-trans ldmatrix over Ah/Al ([j][c] row-major).
            // j>=S_ columns are discarded at extraction (column containment),
            // so concurrent smS writes / zero rows there are harmless.
            for (int mi = 1; mi >= 0; mi--) {
                if (mi == 1 && !fullM) continue;
                float sc4[4][4];
                #pragma unroll
                for (int jt = 0; jt < 4; jt++)
                    #pragma unroll
                    for (int rr = 0; rr < 4; rr++) sc4[jt][rr] = 0.f;

                #pragma unroll
                for (int ksg = 0; ksg < 2; ksg++) {
                    uint32_t tah[4][2], tal[4][2];
                    #pragma unroll
                    for (int k = 0; k < 4; k++) {
                        int ks = ksg * 4 + k;
                        split_pack(c[mi][ks][0], c[mi][ks][1], tah[k][0], tal[k][0]);
                        split_pack(c[mi][ks][2], c[mi][ks][3], tah[k][1], tal[k][1]);
                    }
                    #pragma unroll
                    for (int jt = 0; jt < 4; jt++) {
                        const int J0 = mrow * 32 + mi * 16 - 8 + jt * 8;
                        if (J0 < 0) continue;          // only mrow=0,mi=0,jt=0
                        const uint32_t baddr = sbase
                            + (uint32_t)((J0 + (lane & 7)) * SAH
                                         + nhalf * 64 + ksg * 32
                                         + ((lane >> 3) << 3)) * 2;
                        uint32_t bh4[4], bl4[4];
                        ldm4(bh4, baddr);
                        ldm4(bl4, baddr + ALOFSB);
                        #pragma unroll
                        for (int k = 0; k < 4; k++) {
                            mma_k8(sc4[jt], tah[k][0], tah[k][1], bh4[k]);
                            mma_k8(sc4[jt], tah[k][0], tah[k][1], bl4[k]);
                            mma_k8(sc4[jt], tal[k][0], tal[k][1], bh4[k]);
                        }
                    }
                }
                // band extraction: D row = g/g+8, col j = J0 + 2cq + (rr&1)
                #pragma unroll
                for (int jt = 0; jt < 4; jt++) {
                    const int J0 = mrow * 32 + mi * 16 - 8 + jt * 8;
                    #pragma unroll
                    for (int rr = 0; rr < 4; rr++) {
                        int r = mrow * 32 + mi * 16 + ((rr >> 1) << 3) + g;
                        int j = J0 + 2 * cq + (rr & 1);
                        int m = r + 2 - j;
                        if (r < S_ && (unsigned)j < (unsigned)S_ && (unsigned)m <= 4u)
                            smS[nhalf * 800 + r * 8 + m] = sc4[jt][rr];
                    }
                }
            }
            __syncthreads();
            if (tid < S_) {
                int s = tid;
                float sc[5];
                #pragma unroll
                for (int m = 0; m < 5; m++)
                    sc[m] = (smS[s * 8 + m] + smS[800 + s * 8 + m]) * INV_SQRT_H;
                float mx = sc[0];
                #pragma unroll
                for (int m = 1; m < 5; m++) mx = fmaxf(mx, sc[m]);
                float e5[5], sum = 0.f;
                #pragma unroll
                for (int m = 0; m < 5; m++) { e5[m] = __expf(sc[m] - mx); sum += e5[m]; }
                float rs = 1.f / sum;
                float* wp = wout + ((long long)bb * S_ + s) * 5;
                #pragma unroll
                for (int m = 0; m < 5; m++) {
                    float wmm = e5[m] * rs;
                    wp[m] = wmm;
                    smS[s * 8 + m] = wmm;
                }
            }
            #pragma unroll
            for (int mi = 0; mi < 2; mi++)
                #pragma unroll
                for (int nt = 0; nt < 8; nt++)
                    #pragma unroll
                    for (int rr = 0; rr < 4; rr++) c[mi][nt][rr] = 0.f;
        }

        cp_wait0();
        __syncthreads();
    }

    // ---- p epilogue: write p fp32 into (now free) staging region ----
    float* pbuf = sm + WB_F;                   // [100][stride 33]
    if (wid < 7) {
        #pragma unroll
        for (int hi = 0; hi < 2; hi++) {
            int r = wid * 16 + hi * 8 + g;
            if (r < S_) {
                #pragma unroll
                for (int nt = 0; nt < 4; nt++) {
                    int col = nt * 8 + 2 * cq;
                    pbuf[r * 33 + col]     = c[0][nt][hi * 2 + 0];
                    pbuf[r * 33 + col + 1] = c[0][nt][hi * 2 + 1];
                }
            }
        }
    }
    __syncthreads();

    // ---- final: mid = relu(banded avg of p + cb2); out = mid @ W3 + b3 ----
    const float w3a = sW3[lane * 2 + 0];
    const float w3b = sW3[lane * 2 + 1];
    const float cb2l = cb2s[lane];
    const float b30 = sb3[0], b31 = sb3[1];

    for (int s = wid; s < S_; s += 8) {
        float mid = cb2l;
        #pragma unroll
        for (int m = 0; m < 5; m++) {
            int j = s + 2 - m;
            if (j >= 0 && j < S_)
                mid = fmaf(smS[s * 8 + m], pbuf[j * 33 + lane], mid);
        }
        mid = fmaxf(mid, 0.f);
        float p0 = mid * w3a;
        float p1 = mid * w3b;
        #pragma unroll
        for (int off = 16; off > 0; off >>= 1) {
            p0 += __shfl_xor_sync(0xffffffffu, p0, off);
            p1 += __shfl_xor_sync(0xffffffffu, p1, off);
        }
        if (lane == 0) {
            float* op = out + ((long long)bb * S_ + s) * 2;
            op[0] = p0 + b30;
            op[1] = p1 + b31;
        }
    }
}

extern "C" void kernel_launch(void* const* d_in, const int* in_sizes, int n_in,
                              void* d_out, int out_size)
{
    const float* x  = (const float*)d_in[0];
    const float* W1 = (const float*)d_in[1];
    const float* b1 = (const float*)d_in[2];
    const float* Wq = (const float*)d_in[3];
    const float* Wk = (const float*)d_in[4];
    const float* Wv = (const float*)d_in[5];
    const float* bv = (const float*)d_in[6];
    const float* W2 = (const float*)d_in[7];
    const float* b2 = (const float*)d_in[8];
    const float* W3 = (const float*)d_in[9];
    const float* b3 = (const float*)d_in[10];
    const float* pe = (const float*)d_in[11];

    float* out  = (float*)d_out;                    // (B,S,2)
    float* wout = out + (long long)B_ * S_ * OUT_;  // (B,S,1,5)

    cudaFuncSetAttribute(exrest_fused_kernel,
                         cudaFuncAttributeMaxDynamicSharedMemorySize, SMEM_BYTES);

    prep_all<<<29, 256>>>(W1, Wq, Wk, Wv, W2, bv, b2);
    exrest_fused_kernel<<<B_, NTHREADS, SMEM_BYTES>>>(
        x, b1, W3, b3, pe, out, wout);
}